// round 11
// baseline (speedup 1.0000x reference)
#include <cuda_runtime.h>

#define N_NODES 100000
#define N_EDGES 1600000
#define HIDDEN  128
#define OUT_DIM 400
#define NTHR 512
#define MAX_RESIDENT_BLOCKS (148 * 3)   // matches __launch_bounds__(NTHR, 3)

// Scratch (__device__ globals; allocation-free rule)
__device__ float2 d_vd[N_NODES];    // {v accumulation, dinv}
__device__ float  d_deg[N_NODES];   // in-degree; reset each run by prep phase
__device__ float  d_a[N_NODES];     // dinv * x
__device__ float  d_u[N_NODES];     // sum over out-edges of dinv[col]; reset by accum phase
__device__ float  d_g[HIDDEN];      // sum_i t[i] * relu(s[i]*W1 + b1)
__device__ unsigned int d_bar_count;
__device__ unsigned int d_bar_gen;  // monotonically increasing across replays (safe)

// 8B vector atomic: {v,dinv} += {addv, 0}; returns old dinv (element-wise
// atomic; dinv>0 so the +0.0 lane is an exact read).
__device__ __forceinline__ float atomv2_add_ret_dinv(float2* p, float addv) {
    float ox, oy;
    asm volatile("atom.global.add.v2.f32 {%0,%1}, [%2], {%3,%4};"
                 : "=f"(ox), "=f"(oy)
                 : "l"(p), "f"(addv), "f"(0.0f)
                 : "memory");
    return oy;
}

// Software grid barrier (all blocks resident by construction).
__device__ __forceinline__ void grid_sync(unsigned& gen) {
    __syncthreads();
    if (threadIdx.x == 0) {
        unsigned target = gen + 1;
        __threadfence();
        if (atomicAdd(&d_bar_count, 1u) == gridDim.x - 1) {
            atomicExch(&d_bar_count, 0u);
            __threadfence();
            atomicExch(&d_bar_gen, target);
        } else {
            unsigned g;
            do {
                asm volatile("ld.acquire.gpu.u32 %0, [%1];" : "=r"(g) : "l"(&d_bar_gen));
            } while ((int)(g - target) < 0);
        }
    }
    gen += 1;
    __syncthreads();
}

__global__ void __launch_bounds__(NTHR, 3) k_fused(
    const float* __restrict__ x,
    const int*   __restrict__ row,
    const int*   __restrict__ col,
    const float* __restrict__ W1,
    const float* __restrict__ b1,
    const float* __restrict__ W2,
    const float* __restrict__ b2,
    float* __restrict__ out)
{
    __shared__ float    ss[4][128];
    __shared__ float    st[4][128];
    __shared__ float    s_red[4];
    __shared__ unsigned s_gen0;

    const int tid    = threadIdx.x;
    const int gtid   = blockIdx.x * NTHR + tid;
    const int stride = gridDim.x * NTHR;

    // Snapshot barrier generation. Race-free: gen can only advance after all
    // blocks reach barrier 1, and every block snapshots before its barrier-1
    // arrival.
    if (tid == 0) {
        unsigned g;
        asm volatile("ld.acquire.gpu.u32 %0, [%1];" : "=r"(g) : "l"(&d_bar_gen));
        s_gen0 = g;
    }
    __syncthreads();
    unsigned gen = s_gen0;

    const int4* r4 = (const int4*)row;
    const int4* c4 = (const int4*)col;

    // ---- Phase 1: in-degree histogram over destinations (4 edges/thread) ----
    for (int i = gtid; i < N_EDGES / 4; i += stride) {
        int4 c = c4[i];
        atomicAdd(&d_deg[c.x], 1.0f);
        atomicAdd(&d_deg[c.y], 1.0f);
        atomicAdd(&d_deg[c.z], 1.0f);
        atomicAdd(&d_deg[c.w], 1.0f);
    }
    grid_sync(gen);

    // ---- Phase 2: dinv = rsqrt(deg+1); vd={0,dinv}; a=dinv*x; reset deg; zero g ----
    for (int i = gtid; i < N_NODES; i += stride) {
        float dv = rsqrtf(d_deg[i] + 1.0f);
        d_deg[i] = 0.0f;                    // self-reset for next replay
        d_vd[i]  = make_float2(0.0f, dv);
        d_a[i]   = dv * x[i];
    }
    if (gtid < HIDDEN) d_g[gtid] = 0.0f;
    grid_sync(gen);

    // ---- Phase 3: edge pass, 3 random lane-ops/edge ----
    for (int i = gtid; i < N_EDGES / 4; i += stride) {
        int4 r = r4[i];
        int4 c = c4[i];

        float a0 = __ldg(&d_a[r.x]), a1 = __ldg(&d_a[r.y]);
        float a2 = __ldg(&d_a[r.z]), a3 = __ldg(&d_a[r.w]);

        float dc0 = atomv2_add_ret_dinv(&d_vd[c.x], a0);
        float dc1 = atomv2_add_ret_dinv(&d_vd[c.y], a1);
        float dc2 = atomv2_add_ret_dinv(&d_vd[c.z], a2);
        float dc3 = atomv2_add_ret_dinv(&d_vd[c.w], a3);

        atomicAdd(&d_u[r.x], dc0);
        atomicAdd(&d_u[r.y], dc1);
        atomicAdd(&d_u[r.z], dc2);
        atomicAdd(&d_u[r.w], dc3);
    }
    grid_sync(gen);

    // ---- Phase 4: g[f] += sum_i t[i] * relu(s[i]*W1[f] + b1[f]) ----
    // 4 independent 128-node tiles per block (sub = tid/128), feature = tid%128.
    {
        const int f   = tid & 127;
        const int sub = tid >> 7;
        const float w  = W1[f];
        const float bb = b1[f];
        float acc = 0.0f;

        for (int tbase = blockIdx.x * 4; tbase * 128 < N_NODES; tbase += gridDim.x * 4) {
            int idx = (tbase + sub) * 128 + f;
            float ssv = 0.0f, stv = 0.0f;
            if (idx < N_NODES) {
                float2 vd = d_vd[idx];
                float dv = vd.y;
                ssv = dv * (vd.x + dv * x[idx]);
                stv = dv * (d_u[idx] + dv);
                d_u[idx] = 0.0f;            // self-reset for next replay
            }
            ss[sub][f] = ssv;
            st[sub][f] = stv;
            __syncthreads();
#pragma unroll 16
            for (int j = 0; j < 128; j++) {
                acc += st[sub][j] * fmaxf(fmaf(ss[sub][j], w, bb), 0.0f);
            }
            __syncthreads();
        }

        // Block-level reduction across the 4 subs, one atomic per feature.
        if (blockIdx.x * 4 * 128 < N_NODES) {
            ss[sub][f] = acc;
            __syncthreads();
            if (sub == 0) {
                atomicAdd(&d_g[f], ss[0][f] + ss[1][f] + ss[2][f] + ss[3][f]);
            }
        }
    }
    grid_sync(gen);

    // ---- Phase 5: out[k] = b2[k] + (1/N) * sum_f g[f] * W2[f,k] ----
    for (int k = blockIdx.x; k < OUT_DIM; k += gridDim.x) {
        float p = 0.0f;
        if (tid < 128) p = d_g[tid] * W2[tid * OUT_DIM + k];
        p += __shfl_down_sync(0xffffffffu, p, 16);
        p += __shfl_down_sync(0xffffffffu, p, 8);
        p += __shfl_down_sync(0xffffffffu, p, 4);
        p += __shfl_down_sync(0xffffffffu, p, 2);
        p += __shfl_down_sync(0xffffffffu, p, 1);
        if (tid < 128 && (tid & 31) == 0) s_red[tid >> 5] = p;
        __syncthreads();
        if (tid == 0) {
            out[k] = b2[k] + (s_red[0] + s_red[1] + s_red[2] + s_red[3])
                             * (1.0f / (float)N_NODES);
        }
        __syncthreads();
    }
}

// ---------------------------------------------------------------------------
extern "C" void kernel_launch(void* const* d_in, const int* in_sizes, int n_in,
                              void* d_out, int out_size) {
    const float* x  = (const float*)d_in[0];        // [N, 1]
    const int*   ei = (const int*)d_in[1];          // [2, E]: row then col
    const float* W1 = (const float*)d_in[2];        // [1, 128]
    const float* b1 = (const float*)d_in[3];        // [128]
    const float* W2 = (const float*)d_in[4];        // [128, 400]
    const float* b2 = (const float*)d_in[5];        // [400]
    float* out = (float*)d_out;                     // [400]

    const int* row = ei;
    const int* col = ei + N_EDGES;

    // Deadlock-safe persistent grid: min of the occupancy-derived resident
    // block count and the __launch_bounds__-implied cap.
    int blocks_per_sm = 0;
    cudaOccupancyMaxActiveBlocksPerMultiprocessor(&blocks_per_sm, k_fused, NTHR, 0);
    if (blocks_per_sm < 1) blocks_per_sm = 1;
    int sm_count = 0;
    cudaDeviceGetAttribute(&sm_count, cudaDevAttrMultiProcessorCount, 0);
    if (sm_count < 1) sm_count = 1;
    int grid = blocks_per_sm * sm_count;
    if (grid > MAX_RESIDENT_BLOCKS) grid = MAX_RESIDENT_BLOCKS;

    k_fused<<<grid, NTHR>>>(x, row, col, W1, b1, W2, b2, out);
}

// round 12
// speedup vs baseline: 1.2164x; 1.2164x over previous
#include <cuda_runtime.h>

#define N_NODES 100000
#define N_EDGES 1600000
#define HIDDEN  128
#define OUT_DIM 400

// Scratch (__device__ globals; allocation-free rule). All arrays are
// self-resetting: zero-initialized at module load, and every kernel_launch
// restores the zero invariant for the next call (graph-replay safe).
__device__ float2 d_vd[N_NODES];    // {v accumulation, dinv}; set by k_prep
__device__ float  d_deg[N_NODES];   // in-degree; reset by k_prep after use
__device__ float  d_a[N_NODES];     // dinv * x
__device__ float  d_u[N_NODES];     // sum over out-edges of dinv[col]; reset by k_accum_g
__device__ float  d_g[HIDDEN];      // zeroed by k_prep; consumed by k_out

// 8B vector atomic: {v,dinv} += {addv, 0}; returns old dinv (element-wise
// atomic; dinv>0 so the +0.0 lane is an exact read).
__device__ __forceinline__ float atomv2_add_ret_dinv(float2* p, float addv) {
    float ox, oy;
    asm volatile("atom.global.add.v2.f32 {%0,%1}, [%2], {%3,%4};"
                 : "=f"(ox), "=f"(oy)
                 : "l"(p), "f"(addv), "f"(0.0f)
                 : "memory");
    return oy;
}

// ---------------------------------------------------------------------------
// Pass 1: in-degree histogram over destinations. 8 edges/thread (2x int4).
__global__ void k_deg(const int* __restrict__ col) {
    int i = blockIdx.x * blockDim.x + threadIdx.x;
    if (i < N_EDGES / 8) {
        const int4* c4 = (const int4*)col;
        int4 c0 = c4[2 * i];
        int4 c1 = c4[2 * i + 1];
        atomicAdd(&d_deg[c0.x], 1.0f);
        atomicAdd(&d_deg[c0.y], 1.0f);
        atomicAdd(&d_deg[c0.z], 1.0f);
        atomicAdd(&d_deg[c0.w], 1.0f);
        atomicAdd(&d_deg[c1.x], 1.0f);
        atomicAdd(&d_deg[c1.y], 1.0f);
        atomicAdd(&d_deg[c1.z], 1.0f);
        atomicAdd(&d_deg[c1.w], 1.0f);
    }
}

// Pass 2: dinv = rsqrt(deg+1) (self loop folded in); vd = {0, dinv};
// a = dinv*x; reset deg for the next replay; zero g.
__global__ void k_prep(const float* __restrict__ x) {
    int i = blockIdx.x * blockDim.x + threadIdx.x;
    if (i < N_NODES) {
        float dv = rsqrtf(d_deg[i] + 1.0f);
        d_deg[i] = 0.0f;                    // self-reset
        d_vd[i]  = make_float2(0.0f, dv);
        d_a[i]   = dv * x[i];
    }
    if (i < HIDDEN) d_g[i] = 0.0f;
}

// Pass 3: main edge pass, 3 random lane-ops per edge, 4 edges/thread:
//   a_r = a[row]                       (gather)
//   {v[col],dinv[col]} += {a_r, 0}     (v2 atomic, returns dinv[col])
//   u[row] += dinv[col]                (red)
__global__ void k_edges(const int* __restrict__ row,
                        const int* __restrict__ col) {
    int i = blockIdx.x * blockDim.x + threadIdx.x;
    if (i >= N_EDGES / 4) return;
    int4 r = ((const int4*)row)[i];
    int4 c = ((const int4*)col)[i];

    float a0 = __ldg(&d_a[r.x]), a1 = __ldg(&d_a[r.y]);
    float a2 = __ldg(&d_a[r.z]), a3 = __ldg(&d_a[r.w]);

    float dc0 = atomv2_add_ret_dinv(&d_vd[c.x], a0);
    float dc1 = atomv2_add_ret_dinv(&d_vd[c.y], a1);
    float dc2 = atomv2_add_ret_dinv(&d_vd[c.z], a2);
    float dc3 = atomv2_add_ret_dinv(&d_vd[c.w], a3);

    atomicAdd(&d_u[r.x], dc0);
    atomicAdd(&d_u[r.y], dc1);
    atomicAdd(&d_u[r.z], dc2);
    atomicAdd(&d_u[r.w], dc3);
}

// Pass 4: finalize s,t on the fly and accumulate
//   s[i] = dinv[i]*(v[i] + dinv[i]*x[i]);  t[i] = dinv[i]*(u[i] + dinv[i])
//   g[f] += sum_i t[i] * relu(s[i]*W1[f] + b1[f])
// blockDim = 128 (one feature per thread); 128-node tiles staged in smem.
// Also resets u[i] = 0 for the next replay.
__global__ void k_accum_g(const float* __restrict__ x,
                          const float* __restrict__ W1,
                          const float* __restrict__ b1) {
    __shared__ float ss[128];
    __shared__ float st[128];
    int f = threadIdx.x;
    float w  = W1[f];
    float bb = b1[f];
    float acc = 0.0f;

    for (int base = blockIdx.x * 128; base < N_NODES; base += gridDim.x * 128) {
        int idx = base + f;
        __syncthreads();
        if (idx < N_NODES) {
            float2 vd = d_vd[idx];
            float dv = vd.y;
            ss[f] = dv * (vd.x + dv * x[idx]);
            st[f] = dv * (d_u[idx] + dv);
            d_u[idx] = 0.0f;                // self-reset
        } else {
            ss[f] = 0.0f;
            st[f] = 0.0f;
        }
        __syncthreads();
#pragma unroll 16
        for (int j = 0; j < 128; j++) {
            acc += st[j] * fmaxf(fmaf(ss[j], w, bb), 0.0f);
        }
    }
    atomicAdd(&d_g[f], acc);
}

// Pass 5: out[k] = b2[k] + (1/N) * sum_f g[f] * W2[f, k]
__global__ void k_out(const float* __restrict__ W2,
                      const float* __restrict__ b2,
                      float* __restrict__ out) {
    __shared__ float gs[HIDDEN];
    if (threadIdx.x < HIDDEN) gs[threadIdx.x] = d_g[threadIdx.x];
    __syncthreads();
    int k = blockIdx.x * blockDim.x + threadIdx.x;
    if (k < OUT_DIM) {
        float acc = 0.0f;
#pragma unroll 16
        for (int f = 0; f < HIDDEN; f++) {
            acc = fmaf(gs[f], W2[f * OUT_DIM + k], acc);
        }
        out[k] = b2[k] + acc * (1.0f / (float)N_NODES);
    }
}

// ---------------------------------------------------------------------------
extern "C" void kernel_launch(void* const* d_in, const int* in_sizes, int n_in,
                              void* d_out, int out_size) {
    const float* x  = (const float*)d_in[0];        // [N, 1]
    const int*   ei = (const int*)d_in[1];          // [2, E]: row then col
    const float* W1 = (const float*)d_in[2];        // [1, 128]
    const float* b1 = (const float*)d_in[3];        // [128]
    const float* W2 = (const float*)d_in[4];        // [128, 400]
    const float* b2 = (const float*)d_in[5];        // [400]
    float* out = (float*)d_out;                     // [400]

    const int* row = ei;
    const int* col = ei + N_EDGES;

    k_deg    <<<(N_EDGES / 8 + 255) / 256, 256>>>(col);
    k_prep   <<<(N_NODES + 255) / 256, 256>>>(x);
    k_edges  <<<(N_EDGES / 4 + 255) / 256, 256>>>(row, col);
    k_accum_g<<<304, 128>>>(x, W1, b1);
    k_out    <<<2, 256>>>(W2, b2, out);
}